// round 5
// baseline (speedup 1.0000x reference)
#include <cuda_runtime.h>
#include <cuda_bf16.h>

// Problem constants
#define BB 2
#define SS 2048
#define DD 128
#define HH 8
#define HDIM 16
#define DFF 512
#define MROWS (BB*SS)     // 4096

// ---------------- scratch (device globals; no allocation allowed) -------------
__device__ float g_q[BB*HH*SS*HDIM];
__device__ float g_k[BB*HH*SS*HDIM];
__device__ float g_v[BB*HH*SS*HDIM];
__device__ float g_attn[BB*SS*DD];
__device__ float g_r1[BB*SS*DD];
__device__ float g_r2[BB*SS*DD];
__device__ float g_ln[BB*SS*DD];
__device__ float g_h[BB*SS*DFF];

// ---------------- helpers -----------------------------------------------------
__device__ __forceinline__ unsigned pack_bf16x2(float lo, float hi) {
    unsigned r;
    asm("cvt.rn.bf16x2.f32 %0, %1, %2;" : "=r"(r) : "f"(hi), "f"(lo));
    return r;
}
__device__ __forceinline__ float ex2(float x) {
    float y;
    asm("ex2.approx.ftz.f32 %0, %1;" : "=f"(y) : "f"(x));
    return y;
}
__device__ __forceinline__ unsigned tf32(float x) {
    unsigned r;
    asm("cvt.rna.tf32.f32 %0, %1;" : "=r"(r) : "f"(x));
    return r;
}
__device__ __forceinline__ void mma_bf16(
    float& c0, float& c1, float& c2, float& c3,
    unsigned a0, unsigned a1, unsigned a2, unsigned a3,
    unsigned b0, unsigned b1)
{
    asm("mma.sync.aligned.m16n8k16.row.col.f32.bf16.bf16.f32 "
        "{%0,%1,%2,%3},{%4,%5,%6,%7},{%8,%9},{%0,%1,%2,%3};"
        : "+f"(c0), "+f"(c1), "+f"(c2), "+f"(c3)
        : "r"(a0), "r"(a1), "r"(a2), "r"(a3), "r"(b0), "r"(b1));
}
__device__ __forceinline__ void mma_tf32(
    float& c0, float& c1, float& c2, float& c3,
    unsigned a0, unsigned a1, unsigned a2, unsigned a3,
    unsigned b0, unsigned b1)
{
    asm("mma.sync.aligned.m16n8k8.row.col.f32.tf32.tf32.f32 "
        "{%0,%1,%2,%3},{%4,%5,%6,%7},{%8,%9},{%0,%1,%2,%3};"
        : "+f"(c0), "+f"(c1), "+f"(c2), "+f"(c3)
        : "r"(a0), "r"(a1), "r"(a2), "r"(a3), "r"(b0), "r"(b1));
}

// ---------------- W-resident zero-sync tf32 GEMM ------------------------------
// out = A(MxK) @ W(KxN) + epilogue.  Block: 128 thr, 4 warps, BM=64.
// Whole K x BN weight panel staged to smem once (1 sync); A fragments are
// loaded straight from global into mma registers -> the mainloop has NO
// barriers and NO cross-thread deps; latency hidden by unrolled MLP.
// Smem stride BN+8: B-frag LDS bank = t*8+g+c (mod 32) -> conflict-free.
// EPI: 0 plain  1 +bias+res  2 relu(+bias)
template<int K, int N, int BN, int EPI>
__global__ void __launch_bounds__(128) gemm_tc2_kernel(
    const float* __restrict__ A, const float* __restrict__ W,
    const float* __restrict__ bias, const float* __restrict__ res,
    float* __restrict__ out)
{
    constexpr int WSTR = BN + 8;
    constexpr int NT = BN / 8;
    extern __shared__ unsigned Ws[];   // [K][WSTR]
    const int tid = threadIdx.x, warp = tid >> 5, lane = tid & 31;
    const int g = lane >> 2, t = lane & 3;
    const int bm = blockIdx.y * 64, bn = blockIdx.x * BN;

    // stage whole weight panel (fp32 -> tf32)
    for (int i = tid; i < K * (BN / 4); i += 128) {
        int row = i / (BN / 4), c = (i % (BN / 4)) * 4;
        float4 w4 = *(const float4*)&W[(size_t)row * N + bn + c];
        uint4 u = {tf32(w4.x), tf32(w4.y), tf32(w4.z), tf32(w4.w)};
        *(uint4*)&Ws[row * WSTR + c] = u;
    }
    __syncthreads();

    float acc[NT][4] = {};
    const float* A0 = A + (size_t)(bm + warp * 16 + g) * K;
    const float* A1 = A0 + 8 * K;

#pragma unroll 8
    for (int kt = 0; kt < K; kt += 16) {
#pragma unroll
        for (int kh = 0; kh < 2; kh++) {
            const int kb = kt + kh * 8;
            unsigned a0 = tf32(A0[kb + t]);
            unsigned a1 = tf32(A1[kb + t]);
            unsigned a2 = tf32(A0[kb + t + 4]);
            unsigned a3 = tf32(A1[kb + t + 4]);
#pragma unroll
            for (int j = 0; j < NT; j++) {
                unsigned b0 = Ws[(kb + t) * WSTR + j * 8 + g];
                unsigned b1 = Ws[(kb + t + 4) * WSTR + j * 8 + g];
                mma_tf32(acc[j][0], acc[j][1], acc[j][2], acc[j][3],
                         a0, a1, a2, a3, b0, b1);
            }
        }
    }

    const int r0 = bm + warp * 16 + g;
#pragma unroll
    for (int j = 0; j < NT; j++) {
        int c0 = bn + j * 8 + 2 * t;
        if (EPI == 1) {
            float2 bi = *(const float2*)&bias[c0];
            float2 rA = *(const float2*)&res[(size_t)r0 * N + c0];
            float2 rB = *(const float2*)&res[(size_t)(r0 + 8) * N + c0];
            float2 oA = {acc[j][0] + bi.x + rA.x, acc[j][1] + bi.y + rA.y};
            float2 oB = {acc[j][2] + bi.x + rB.x, acc[j][3] + bi.y + rB.y};
            *(float2*)&out[(size_t)r0 * N + c0] = oA;
            *(float2*)&out[(size_t)(r0 + 8) * N + c0] = oB;
        } else if (EPI == 2) {
            float2 bi = *(const float2*)&bias[c0];
            float2 oA = {fmaxf(acc[j][0] + bi.x, 0.f), fmaxf(acc[j][1] + bi.y, 0.f)};
            float2 oB = {fmaxf(acc[j][2] + bi.x, 0.f), fmaxf(acc[j][3] + bi.y, 0.f)};
            *(float2*)&out[(size_t)r0 * N + c0] = oA;
            *(float2*)&out[(size_t)(r0 + 8) * N + c0] = oB;
        } else {
            *(float2*)&out[(size_t)r0 * N + c0] = {acc[j][0], acc[j][1]};
            *(float2*)&out[(size_t)(r0 + 8) * N + c0] = {acc[j][2], acc[j][3]};
        }
    }
}

// ---------------- W-resident fused QKV projection (scatter epilogue) ----------
// grid (6, 64): blockIdx.x>>1 selects {Q,K,V}; Q may use a different A
// (cross-attn quirk).  Scatter col c -> h=c&7, hd=c>>3 into [b][h][s][hd].
__global__ void __launch_bounds__(128) gemm_qkv_tc2_kernel(
    const float* __restrict__ Aq, const float* __restrict__ Akv,
    const float* __restrict__ wq, const float* __restrict__ wk,
    const float* __restrict__ wv,
    float* __restrict__ qo, float* __restrict__ ko, float* __restrict__ vo)
{
    const int which = blockIdx.x >> 1;
    const float* A = (which == 0) ? Aq : Akv;
    const float* W = (which == 0) ? wq : ((which == 1) ? wk : wv);
    float* out     = (which == 0) ? qo : ((which == 1) ? ko : vo);

    constexpr int WSTR = 72;
    extern __shared__ unsigned Ws[];   // [128][72]
    const int tid = threadIdx.x, warp = tid >> 5, lane = tid & 31;
    const int g = lane >> 2, t = lane & 3;
    const int bm = blockIdx.y * 64, bn = (blockIdx.x & 1) * 64;

    for (int i = tid; i < DD * 16; i += 128) {
        int row = i / 16, c = (i % 16) * 4;
        float4 w4 = *(const float4*)&W[(size_t)row * DD + bn + c];
        uint4 u = {tf32(w4.x), tf32(w4.y), tf32(w4.z), tf32(w4.w)};
        *(uint4*)&Ws[row * WSTR + c] = u;
    }
    __syncthreads();

    float acc[8][4] = {};
    const float* A0 = A + (size_t)(bm + warp * 16 + g) * DD;
    const float* A1 = A0 + 8 * DD;

#pragma unroll
    for (int kt = 0; kt < DD; kt += 16) {
#pragma unroll
        for (int kh = 0; kh < 2; kh++) {
            const int kb = kt + kh * 8;
            unsigned a0 = tf32(A0[kb + t]);
            unsigned a1 = tf32(A1[kb + t]);
            unsigned a2 = tf32(A0[kb + t + 4]);
            unsigned a3 = tf32(A1[kb + t + 4]);
#pragma unroll
            for (int j = 0; j < 8; j++) {
                unsigned b0 = Ws[(kb + t) * WSTR + j * 8 + g];
                unsigned b1 = Ws[(kb + t + 4) * WSTR + j * 8 + g];
                mma_tf32(acc[j][0], acc[j][1], acc[j][2], acc[j][3],
                         a0, a1, a2, a3, b0, b1);
            }
        }
    }

    const int r0 = bm + warp * 16 + g;
    const int bb0 = r0 >> 11, ss0 = r0 & (SS - 1);
    const int r1 = r0 + 8;
    const int bb1 = r1 >> 11, ss1 = r1 & (SS - 1);
#pragma unroll
    for (int j = 0; j < 8; j++) {
#pragma unroll
        for (int u = 0; u < 2; u++) {
            int c = bn + j * 8 + 2 * t + u;
            int hh = c & 7, hd = c >> 3;
            out[(((size_t)(bb0 * HH + hh) * SS) + ss0) * HDIM + hd] = acc[j][u];
            out[(((size_t)(bb1 * HH + hh) * SS) + ss1) * HDIM + hd] = acc[j][2 + u];
        }
    }
}

// ---------------- flash attention with bf16 tensor cores ----------------------
// grid (S/64, B*H), 128 threads (4 warps), each warp owns 16 query rows.
#define VSTRIDE 136

__global__ void __launch_bounds__(128) attn_mma_kernel(
    const float* __restrict__ q, const float* __restrict__ k,
    const float* __restrict__ v, float* __restrict__ out)
{
    __shared__ unsigned Ks[128][8];              // [key][dim-pair] bf16x2
    __shared__ __nv_bfloat16 Vs[16][VSTRIDE];    // [dim][key] transposed, padded
    const int tid = threadIdx.x, w = tid >> 5, lane = tid & 31;
    const int bh = blockIdx.y, b = bh >> 3, h = bh & 7;
    const int g = lane >> 2, c = lane & 3;
    const size_t head = (size_t)bh * SS;
    const int qrow = blockIdx.x * 64 + w * 16;

    const float sc = 0.25f * 1.4426950408889634f;
    unsigned qa[4];
    {
        const float* r0 = q + (head + qrow + g) * HDIM;
        const float* r1 = r0 + 8 * HDIM;
        float2 t;
        t = *(const float2*)(r0 + 2 * c);     qa[0] = pack_bf16x2(t.x * sc, t.y * sc);
        t = *(const float2*)(r1 + 2 * c);     qa[1] = pack_bf16x2(t.x * sc, t.y * sc);
        t = *(const float2*)(r0 + 2 * c + 8); qa[2] = pack_bf16x2(t.x * sc, t.y * sc);
        t = *(const float2*)(r1 + 2 * c + 8); qa[3] = pack_bf16x2(t.x * sc, t.y * sc);
    }

    float o[8] = {0, 0, 0, 0, 0, 0, 0, 0};
    float l0 = 0.f, l1 = 0.f;

    for (int kt = 0; kt < SS / 128; kt++) {
        __syncthreads();
        const float4* ksrc = (const float4*)(k + (head + kt * 128) * HDIM);
        const float4* vsrc = (const float4*)(v + (head + kt * 128) * HDIM);
#pragma unroll
        for (int i = 0; i < 4; i++) {
            int idx = tid + i * 128;
            int key = idx >> 2, f4 = idx & 3;
            float4 t = ksrc[idx];
            Ks[key][f4 * 2]     = pack_bf16x2(t.x, t.y);
            Ks[key][f4 * 2 + 1] = pack_bf16x2(t.z, t.w);
            float4 u = vsrc[idx];
            Vs[f4 * 4 + 0][key] = __float2bfloat16(u.x);
            Vs[f4 * 4 + 1][key] = __float2bfloat16(u.y);
            Vs[f4 * 4 + 2][key] = __float2bfloat16(u.z);
            Vs[f4 * 4 + 3][key] = __float2bfloat16(u.w);
        }
        __syncthreads();

#pragma unroll
        for (int kc = 0; kc < 8; kc++) {
            float s0 = 0, s1 = 0, s2 = 0, s3 = 0, s4 = 0, s5 = 0, s6 = 0, s7 = 0;
            {
                unsigned b0 = Ks[kc * 16 + g][c];
                unsigned b1 = Ks[kc * 16 + g][c + 4];
                mma_bf16(s0, s1, s2, s3, qa[0], qa[1], qa[2], qa[3], b0, b1);
                b0 = Ks[kc * 16 + 8 + g][c];
                b1 = Ks[kc * 16 + 8 + g][c + 4];
                mma_bf16(s4, s5, s6, s7, qa[0], qa[1], qa[2], qa[3], b0, b1);
            }
            float p0 = ex2(s0), p1 = ex2(s1), p2 = ex2(s2), p3 = ex2(s3);
            float p4 = ex2(s4), p5 = ex2(s5), p6 = ex2(s6), p7 = ex2(s7);
            l0 += (p0 + p1) + (p4 + p5);
            l1 += (p2 + p3) + (p6 + p7);
            unsigned A0 = pack_bf16x2(p0, p1);
            unsigned A1 = pack_bf16x2(p2, p3);
            unsigned A2 = pack_bf16x2(p4, p5);
            unsigned A3 = pack_bf16x2(p6, p7);
            unsigned vb0 = *(const unsigned*)&Vs[g][kc * 16 + 2 * c];
            unsigned vb1 = *(const unsigned*)&Vs[g][kc * 16 + 2 * c + 8];
            mma_bf16(o[0], o[1], o[2], o[3], A0, A1, A2, A3, vb0, vb1);
            vb0 = *(const unsigned*)&Vs[8 + g][kc * 16 + 2 * c];
            vb1 = *(const unsigned*)&Vs[8 + g][kc * 16 + 2 * c + 8];
            mma_bf16(o[4], o[5], o[6], o[7], A0, A1, A2, A3, vb0, vb1);
        }
    }

    l0 += __shfl_xor_sync(~0u, l0, 1); l0 += __shfl_xor_sync(~0u, l0, 2);
    l1 += __shfl_xor_sync(~0u, l1, 1); l1 += __shfl_xor_sync(~0u, l1, 2);
    const float inv0 = 1.0f / l0, inv1 = 1.0f / l1;

    float* ob0 = out + ((size_t)(b * SS) + qrow + g) * DD + h;
    float* ob1 = out + ((size_t)(b * SS) + qrow + 8 + g) * DD + h;
    ob0[(2 * c) * HH]     = o[0] * inv0;
    ob0[(2 * c + 1) * HH] = o[1] * inv0;
    ob0[(8 + 2 * c) * HH] = o[4] * inv0;
    ob0[(9 + 2 * c) * HH] = o[5] * inv0;
    ob1[(2 * c) * HH]     = o[2] * inv1;
    ob1[(2 * c + 1) * HH] = o[3] * inv1;
    ob1[(8 + 2 * c) * HH] = o[6] * inv1;
    ob1[(9 + 2 * c) * HH] = o[7] * inv1;
}

// ---------------- custom "layernorm": c / var, var unbiased (N-1) -------------
__global__ void __launch_bounds__(256) ln_kernel(const float* __restrict__ x,
                                                 float* __restrict__ y)
{
    int row  = blockIdx.x * 8 + (threadIdx.x >> 5);
    int lane = threadIdx.x & 31;
    float4 t = ((const float4*)(x + (size_t)row * DD))[lane];
    float s = t.x + t.y + t.z + t.w;
#pragma unroll
    for (int o = 16; o; o >>= 1) s += __shfl_xor_sync(~0u, s, o);
    float m = s * (1.0f / DD);
    float cx = t.x - m, cy = t.y - m, cz = t.z - m, cw = t.w - m;
    float ss = cx * cx + cy * cy + cz * cz + cw * cw;
#pragma unroll
    for (int o = 16; o; o >>= 1) ss += __shfl_xor_sync(~0u, ss, o);
    float inv = (float)(DD - 1) / ss;
    float4 o4 = {cx * inv, cy * inv, cz * inv, cw * inv};
    ((float4*)(y + (size_t)row * DD))[lane] = o4;
}

// ---------------- launch --------------------------------------------------------
extern "C" void kernel_launch(void* const* d_in, const int* in_sizes, int n_in,
                              void* d_out, int out_size) {
    (void)in_sizes; (void)n_in; (void)out_size;
    const float* x_tgt = (const float*)d_in[0];
    const float* enc   = (const float*)d_in[1];
    const float* swq   = (const float*)d_in[2];
    const float* swk   = (const float*)d_in[3];
    const float* swv   = (const float*)d_in[4];
    const float* cwq   = (const float*)d_in[5];
    const float* cwk   = (const float*)d_in[6];
    const float* cwv   = (const float*)d_in[7];
    const float* w1    = (const float*)d_in[8];
    const float* b1    = (const float*)d_in[9];
    const float* w2    = (const float*)d_in[10];
    const float* b2    = (const float*)d_in[11];
    const float* w3    = (const float*)d_in[12];
    const float* b3    = (const float*)d_in[13];
    const float* w4    = (const float*)d_in[14];
    const float* b4    = (const float*)d_in[15];
    float* out = (float*)d_out;

    float *q, *k, *v, *attn, *r1, *r2, *ln, *h;
    cudaGetSymbolAddress((void**)&q,    g_q);
    cudaGetSymbolAddress((void**)&k,    g_k);
    cudaGetSymbolAddress((void**)&v,    g_v);
    cudaGetSymbolAddress((void**)&attn, g_attn);
    cudaGetSymbolAddress((void**)&r1,   g_r1);
    cudaGetSymbolAddress((void**)&r2,   g_r2);
    cudaGetSymbolAddress((void**)&ln,   g_ln);
    cudaGetSymbolAddress((void**)&h,    g_h);

    // dynamic smem sizes (W panel, tf32, stride BN+8)
    const int smQKV = DD * 72 * 4;          // 36864
    const int smEpi = 128 * 40 * 4;         // 20480
    const int smW3  = 128 * 72 * 4;         // 36864
    const int smW4  = 512 * 40 * 4;         // 81920 (> 48K -> needs attribute)
    cudaFuncSetAttribute(gemm_tc2_kernel<512, 128, 32, 1>,
                         cudaFuncAttributeMaxDynamicSharedMemorySize, smW4);

    const dim3 gQKV(6, MROWS / 64);               // fused QKV (tf32 TC)
    const dim3 gEpi(4, MROWS / 64);               // N=128, BN=32
    const dim3 gW3(8, MROWS / 64);                // N=512, BN=64
    const dim3 gW4(4, MROWS / 64);                // K=512 -> N=128, BN=32
    const dim3 gA(SS / 64, BB * HH);              // flash attention

    // ---- self attention: Q,K,V all from x_tgt ----
    gemm_qkv_tc2_kernel<<<gQKV, 128, smQKV>>>(x_tgt, x_tgt, swq, swk, swv, q, k, v);
    attn_mma_kernel<<<gA, 128>>>(q, k, v, attn);
    gemm_tc2_kernel<128, 128, 32, 1><<<gEpi, 128, smEpi>>>(attn, w1, b1, x_tgt, r1);

    // ---- "cross" attention (faithful quirk): Q from enc_out, K/V from x_tgt ----
    gemm_qkv_tc2_kernel<<<gQKV, 128, smQKV>>>(enc, x_tgt, cwq, cwk, cwv, q, k, v);
    attn_mma_kernel<<<gA, 128>>>(q, k, v, attn);
    gemm_tc2_kernel<128, 128, 32, 1><<<gEpi, 128, smEpi>>>(attn, w2, b2, r1, r2);

    // ---- norm + FFN ----
    ln_kernel<<<MROWS / 8, 256>>>(r2, ln);
    gemm_tc2_kernel<128, 512, 64, 2><<<gW3, 128, smW3>>>(ln, w3, b3, nullptr, h);  // relu
    gemm_tc2_kernel<512, 128, 32, 1><<<gW4, 128, smW4>>>(h, w4, b4, r2, out);
}

// round 6
// speedup vs baseline: 1.2556x; 1.2556x over previous
#include <cuda_runtime.h>
#include <cuda_bf16.h>

// Problem constants
#define BB 2
#define SS 2048
#define DD 128
#define HH 8
#define HDIM 16
#define DFF 512
#define MROWS (BB*SS)     // 4096

// ---------------- scratch (device globals; no allocation allowed) -------------
__device__ float g_q1[BB*HH*SS*HDIM];
__device__ float g_k1[BB*HH*SS*HDIM];
__device__ float g_v1[BB*HH*SS*HDIM];
__device__ float g_q2[BB*HH*SS*HDIM];
__device__ float g_k2[BB*HH*SS*HDIM];
__device__ float g_v2[BB*HH*SS*HDIM];
__device__ float g_attn1[BB*SS*DD];
__device__ float g_attn2[BB*SS*DD];
__device__ float g_r1[BB*SS*DD];
__device__ float g_r2[BB*SS*DD];
__device__ float g_ln[BB*SS*DD];
__device__ float g_h[BB*SS*DFF];

// ---------------- helpers -----------------------------------------------------
__device__ __forceinline__ unsigned pack_bf16x2(float lo, float hi) {
    unsigned r;
    asm("cvt.rn.bf16x2.f32 %0, %1, %2;" : "=r"(r) : "f"(hi), "f"(lo));
    return r;
}
__device__ __forceinline__ float ex2(float x) {
    float y;
    asm("ex2.approx.ftz.f32 %0, %1;" : "=f"(y) : "f"(x));
    return y;
}
__device__ __forceinline__ unsigned tf32(float x) {
    unsigned r;
    asm("cvt.rna.tf32.f32 %0, %1;" : "=r"(r) : "f"(x));
    return r;
}
__device__ __forceinline__ void mma_bf16(
    float& c0, float& c1, float& c2, float& c3,
    unsigned a0, unsigned a1, unsigned a2, unsigned a3,
    unsigned b0, unsigned b1)
{
    asm("mma.sync.aligned.m16n8k16.row.col.f32.bf16.bf16.f32 "
        "{%0,%1,%2,%3},{%4,%5,%6,%7},{%8,%9},{%0,%1,%2,%3};"
        : "+f"(c0), "+f"(c1), "+f"(c2), "+f"(c3)
        : "r"(a0), "r"(a1), "r"(a2), "r"(a3), "r"(b0), "r"(b1));
}
__device__ __forceinline__ void mma_tf32(
    float& c0, float& c1, float& c2, float& c3,
    unsigned a0, unsigned a1, unsigned a2, unsigned a3,
    unsigned b0, unsigned b1)
{
    asm("mma.sync.aligned.m16n8k8.row.col.f32.tf32.tf32.f32 "
        "{%0,%1,%2,%3},{%4,%5,%6,%7},{%8,%9},{%0,%1,%2,%3};"
        : "+f"(c0), "+f"(c1), "+f"(c2), "+f"(c3)
        : "r"(a0), "r"(a1), "r"(a2), "r"(a3), "r"(b0), "r"(b1));
}
__device__ __forceinline__ void cp16(unsigned dst, const void* src) {
    asm volatile("cp.async.cg.shared.global [%0], [%1], 16;"
                 :: "r"(dst), "l"(src));
}
__device__ __forceinline__ void cp_commit() {
    asm volatile("cp.async.commit_group;");
}
__device__ __forceinline__ void cp_wait1() {
    asm volatile("cp.async.wait_group 1;");
}

#define ASTR 20           // A-tile smem stride (words): frag LDS conflict-free
#define ATILE (64*ASTR)   // one A stage, words

// ---------------- cp.async-pipelined W-resident tf32 GEMM ---------------------
// out = A(MxK) @ W(KxN) + epilogue.  128 thr, 4 warps, BM=64.
// W panel (K x BN) smem-resident (loaded once, tf32, stride BN+8: frag LDS
// bank = 8t+g -> conflict-free).  A tiles (64x16 fp32) double-buffered via
// cp.async -> load of tile kt+1 overlaps compute of tile kt.
// EPI: 0 plain  1 +bias+res  2 relu(+bias)
template<int K, int N, int BN, int EPI>
__global__ void __launch_bounds__(128) gemm_pipe_kernel(
    const float* __restrict__ A, const float* __restrict__ W,
    const float* __restrict__ bias, const float* __restrict__ res,
    float* __restrict__ out)
{
    constexpr int WSTR = BN + 8;
    constexpr int NT = BN / 8;
    constexpr int KT = K / 16;
    extern __shared__ unsigned smem[];
    unsigned* Ws = smem;                       // [K][WSTR] tf32
    float* As = (float*)(smem + K * WSTR);     // 2 x [64][ASTR] fp32
    const unsigned As_sh = (unsigned)__cvta_generic_to_shared(As);
    const int tid = threadIdx.x, warp = tid >> 5, lane = tid & 31;
    const int g = lane >> 2, t = lane & 3;
    const int bm = blockIdx.y * 64, bn = blockIdx.x * BN;

    // stage whole weight panel (fp32 -> tf32), once
    for (int i = tid; i < K * (BN / 4); i += 128) {
        int row = i / (BN / 4), c = (i % (BN / 4)) * 4;
        float4 w4 = *(const float4*)&W[(size_t)row * N + bn + c];
        uint4 u = {tf32(w4.x), tf32(w4.y), tf32(w4.z), tf32(w4.w)};
        *(uint4*)&Ws[row * WSTR + c] = u;
    }

    // A prefetch: 64 rows x 16 k = 256 x 16B chunks, 2 per thread
    const int arow = tid >> 1;                 // 0..63 (chunk pair rows)
    auto loadA = [&](int kt, int buf) {
#pragma unroll
        for (int i = 0; i < 2; i++) {
            int idx = tid * 2 + i;             // 0..255
            int row = idx >> 2, kc = (idx & 3) * 4;
            cp16(As_sh + (buf * ATILE + row * ASTR + kc) * 4,
                 &A[(size_t)(bm + row) * K + kt * 16 + kc]);
        }
        cp_commit();
    };
    (void)arow;
    loadA(0, 0);

    float acc[NT][4] = {};
    const int ra = warp * 16 + g;

    for (int kt = 0; kt < KT; kt++) {
        if (kt + 1 < KT) loadA(kt + 1, (kt + 1) & 1);
        else cp_commit();                      // empty group keeps wait count right
        cp_wait1();
        __syncthreads();
        const float* Ab = As + (kt & 1) * ATILE;
#pragma unroll
        for (int kh = 0; kh < 16; kh += 8) {
            unsigned a0 = tf32(Ab[ra * ASTR + kh + t]);
            unsigned a1 = tf32(Ab[(ra + 8) * ASTR + kh + t]);
            unsigned a2 = tf32(Ab[ra * ASTR + kh + t + 4]);
            unsigned a3 = tf32(Ab[(ra + 8) * ASTR + kh + t + 4]);
            const int kr = kt * 16 + kh;
#pragma unroll
            for (int j = 0; j < NT; j++) {
                unsigned b0 = Ws[(kr + t) * WSTR + j * 8 + g];
                unsigned b1 = Ws[(kr + t + 4) * WSTR + j * 8 + g];
                mma_tf32(acc[j][0], acc[j][1], acc[j][2], acc[j][3],
                         a0, a1, a2, a3, b0, b1);
            }
        }
        __syncthreads();
    }

    const int r0 = bm + ra;
#pragma unroll
    for (int j = 0; j < NT; j++) {
        int c0 = bn + j * 8 + 2 * t;
        if (EPI == 1) {
            float2 bi = *(const float2*)&bias[c0];
            float2 rA = *(const float2*)&res[(size_t)r0 * N + c0];
            float2 rB = *(const float2*)&res[(size_t)(r0 + 8) * N + c0];
            float2 oA = {acc[j][0] + bi.x + rA.x, acc[j][1] + bi.y + rA.y};
            float2 oB = {acc[j][2] + bi.x + rB.x, acc[j][3] + bi.y + rB.y};
            *(float2*)&out[(size_t)r0 * N + c0] = oA;
            *(float2*)&out[(size_t)(r0 + 8) * N + c0] = oB;
        } else if (EPI == 2) {
            float2 bi = *(const float2*)&bias[c0];
            float2 oA = {fmaxf(acc[j][0] + bi.x, 0.f), fmaxf(acc[j][1] + bi.y, 0.f)};
            float2 oB = {fmaxf(acc[j][2] + bi.x, 0.f), fmaxf(acc[j][3] + bi.y, 0.f)};
            *(float2*)&out[(size_t)r0 * N + c0] = oA;
            *(float2*)&out[(size_t)(r0 + 8) * N + c0] = oB;
        } else {
            *(float2*)&out[(size_t)r0 * N + c0] = {acc[j][0], acc[j][1]};
            *(float2*)&out[(size_t)(r0 + 8) * N + c0] = {acc[j][2], acc[j][3]};
        }
    }
}

// ---------------- ALL-SIX QKV projections in one launch (pipelined) -----------
// Cross-attn Q/K/V depend only on graph inputs, so self + cross project
// together.  grid (12, 64): blockIdx.x>>1 = {sq, sk, sv, cq, ck, cv}
// (cross Q reads enc_out — the reference's quirk).  Scatter col c ->
// h=c&7, hd=c>>3 into [b][h][s][hd].
__global__ void __launch_bounds__(128) gemm_qkv6_kernel(
    const float* __restrict__ x_tgt, const float* __restrict__ enc,
    const float* __restrict__ swq, const float* __restrict__ swk,
    const float* __restrict__ swv, const float* __restrict__ cwq,
    const float* __restrict__ cwk, const float* __restrict__ cwv,
    float* __restrict__ q1, float* __restrict__ k1, float* __restrict__ v1,
    float* __restrict__ q2, float* __restrict__ k2, float* __restrict__ v2)
{
    const int which = blockIdx.x >> 1;
    const float* A = (which == 3) ? enc : x_tgt;
    const float* W; float* out;
    switch (which) {
        case 0: W = swq; out = q1; break;
        case 1: W = swk; out = k1; break;
        case 2: W = swv; out = v1; break;
        case 3: W = cwq; out = q2; break;
        case 4: W = cwk; out = k2; break;
        default: W = cwv; out = v2; break;
    }

    constexpr int WSTR = 72;
    extern __shared__ unsigned smem[];
    unsigned* Ws = smem;                       // [128][72]
    float* As = (float*)(smem + DD * WSTR);
    const unsigned As_sh = (unsigned)__cvta_generic_to_shared(As);
    const int tid = threadIdx.x, warp = tid >> 5, lane = tid & 31;
    const int g = lane >> 2, t = lane & 3;
    const int bm = blockIdx.y * 64, bn = (blockIdx.x & 1) * 64;

    for (int i = tid; i < DD * 16; i += 128) {
        int row = i / 16, c = (i % 16) * 4;
        float4 w4 = *(const float4*)&W[(size_t)row * DD + bn + c];
        uint4 u = {tf32(w4.x), tf32(w4.y), tf32(w4.z), tf32(w4.w)};
        *(uint4*)&Ws[row * WSTR + c] = u;
    }

    auto loadA = [&](int kt, int buf) {
#pragma unroll
        for (int i = 0; i < 2; i++) {
            int idx = tid * 2 + i;
            int row = idx >> 2, kc = (idx & 3) * 4;
            cp16(As_sh + (buf * ATILE + row * ASTR + kc) * 4,
                 &A[(size_t)(bm + row) * DD + kt * 16 + kc]);
        }
        cp_commit();
    };
    loadA(0, 0);

    float acc[8][4] = {};
    const int ra = warp * 16 + g;

    for (int kt = 0; kt < DD / 16; kt++) {
        if (kt + 1 < DD / 16) loadA(kt + 1, (kt + 1) & 1);
        else cp_commit();
        cp_wait1();
        __syncthreads();
        const float* Ab = As + (kt & 1) * ATILE;
#pragma unroll
        for (int kh = 0; kh < 16; kh += 8) {
            unsigned a0 = tf32(Ab[ra * ASTR + kh + t]);
            unsigned a1 = tf32(Ab[(ra + 8) * ASTR + kh + t]);
            unsigned a2 = tf32(Ab[ra * ASTR + kh + t + 4]);
            unsigned a3 = tf32(Ab[(ra + 8) * ASTR + kh + t + 4]);
            const int kr = kt * 16 + kh;
#pragma unroll
            for (int j = 0; j < 8; j++) {
                unsigned b0 = Ws[(kr + t) * WSTR + j * 8 + g];
                unsigned b1 = Ws[(kr + t + 4) * WSTR + j * 8 + g];
                mma_tf32(acc[j][0], acc[j][1], acc[j][2], acc[j][3],
                         a0, a1, a2, a3, b0, b1);
            }
        }
        __syncthreads();
    }

    const int r0 = bm + ra;
    const int bb0 = r0 >> 11, ss0 = r0 & (SS - 1);
    const int r1 = r0 + 8;
    const int bb1 = r1 >> 11, ss1 = r1 & (SS - 1);
#pragma unroll
    for (int j = 0; j < 8; j++) {
#pragma unroll
        for (int u = 0; u < 2; u++) {
            int c = bn + j * 8 + 2 * t + u;
            int hh = c & 7, hd = c >> 3;
            out[(((size_t)(bb0 * HH + hh) * SS) + ss0) * HDIM + hd] = acc[j][u];
            out[(((size_t)(bb1 * HH + hh) * SS) + ss1) * HDIM + hd] = acc[j][2 + u];
        }
    }
}

// ---------------- flash attention (both attentions in one launch) -------------
// grid (S/64, B*H, 2): z=0 self, z=1 cross.  128 thr (4 warps), warp owns
// 16 query rows.  bf16 mma QK^T and PV; no max-subtraction.
#define VSTRIDE 136

__global__ void __launch_bounds__(128) attn_mma_kernel(
    const float* __restrict__ q1, const float* __restrict__ k1,
    const float* __restrict__ v1, float* __restrict__ o1,
    const float* __restrict__ q2, const float* __restrict__ k2,
    const float* __restrict__ v2, float* __restrict__ o2)
{
    const float* q = blockIdx.z ? q2 : q1;
    const float* k = blockIdx.z ? k2 : k1;
    const float* v = blockIdx.z ? v2 : v1;
    float* out     = blockIdx.z ? o2 : o1;

    __shared__ unsigned Ks[128][8];
    __shared__ __nv_bfloat16 Vs[16][VSTRIDE];
    const int tid = threadIdx.x, w = tid >> 5, lane = tid & 31;
    const int bh = blockIdx.y, b = bh >> 3, h = bh & 7;
    const int g = lane >> 2, c = lane & 3;
    const size_t head = (size_t)bh * SS;
    const int qrow = blockIdx.x * 64 + w * 16;

    const float sc = 0.25f * 1.4426950408889634f;
    unsigned qa[4];
    {
        const float* r0 = q + (head + qrow + g) * HDIM;
        const float* r1 = r0 + 8 * HDIM;
        float2 t;
        t = *(const float2*)(r0 + 2 * c);     qa[0] = pack_bf16x2(t.x * sc, t.y * sc);
        t = *(const float2*)(r1 + 2 * c);     qa[1] = pack_bf16x2(t.x * sc, t.y * sc);
        t = *(const float2*)(r0 + 2 * c + 8); qa[2] = pack_bf16x2(t.x * sc, t.y * sc);
        t = *(const float2*)(r1 + 2 * c + 8); qa[3] = pack_bf16x2(t.x * sc, t.y * sc);
    }

    float o[8] = {0, 0, 0, 0, 0, 0, 0, 0};
    float l0 = 0.f, l1 = 0.f;

    for (int kt = 0; kt < SS / 128; kt++) {
        __syncthreads();
        const float4* ksrc = (const float4*)(k + (head + kt * 128) * HDIM);
        const float4* vsrc = (const float4*)(v + (head + kt * 128) * HDIM);
#pragma unroll
        for (int i = 0; i < 4; i++) {
            int idx = tid + i * 128;
            int key = idx >> 2, f4 = idx & 3;
            float4 t = ksrc[idx];
            Ks[key][f4 * 2]     = pack_bf16x2(t.x, t.y);
            Ks[key][f4 * 2 + 1] = pack_bf16x2(t.z, t.w);
            float4 u = vsrc[idx];
            Vs[f4 * 4 + 0][key] = __float2bfloat16(u.x);
            Vs[f4 * 4 + 1][key] = __float2bfloat16(u.y);
            Vs[f4 * 4 + 2][key] = __float2bfloat16(u.z);
            Vs[f4 * 4 + 3][key] = __float2bfloat16(u.w);
        }
        __syncthreads();

#pragma unroll
        for (int kc = 0; kc < 8; kc++) {
            float s0 = 0, s1 = 0, s2 = 0, s3 = 0, s4 = 0, s5 = 0, s6 = 0, s7 = 0;
            {
                unsigned b0 = Ks[kc * 16 + g][c];
                unsigned b1 = Ks[kc * 16 + g][c + 4];
                mma_bf16(s0, s1, s2, s3, qa[0], qa[1], qa[2], qa[3], b0, b1);
                b0 = Ks[kc * 16 + 8 + g][c];
                b1 = Ks[kc * 16 + 8 + g][c + 4];
                mma_bf16(s4, s5, s6, s7, qa[0], qa[1], qa[2], qa[3], b0, b1);
            }
            float p0 = ex2(s0), p1 = ex2(s1), p2 = ex2(s2), p3 = ex2(s3);
            float p4 = ex2(s4), p5 = ex2(s5), p6 = ex2(s6), p7 = ex2(s7);
            l0 += (p0 + p1) + (p4 + p5);
            l1 += (p2 + p3) + (p6 + p7);
            unsigned A0 = pack_bf16x2(p0, p1);
            unsigned A1 = pack_bf16x2(p2, p3);
            unsigned A2 = pack_bf16x2(p4, p5);
            unsigned A3 = pack_bf16x2(p6, p7);
            unsigned vb0 = *(const unsigned*)&Vs[g][kc * 16 + 2 * c];
            unsigned vb1 = *(const unsigned*)&Vs[g][kc * 16 + 2 * c + 8];
            mma_bf16(o[0], o[1], o[2], o[3], A0, A1, A2, A3, vb0, vb1);
            vb0 = *(const unsigned*)&Vs[8 + g][kc * 16 + 2 * c];
            vb1 = *(const unsigned*)&Vs[8 + g][kc * 16 + 2 * c + 8];
            mma_bf16(o[4], o[5], o[6], o[7], A0, A1, A2, A3, vb0, vb1);
        }
    }

    l0 += __shfl_xor_sync(~0u, l0, 1); l0 += __shfl_xor_sync(~0u, l0, 2);
    l1 += __shfl_xor_sync(~0u, l1, 1); l1 += __shfl_xor_sync(~0u, l1, 2);
    const float inv0 = 1.0f / l0, inv1 = 1.0f / l1;

    float* ob0 = out + ((size_t)(b * SS) + qrow + g) * DD + h;
    float* ob1 = out + ((size_t)(b * SS) + qrow + 8 + g) * DD + h;
    ob0[(2 * c) * HH]     = o[0] * inv0;
    ob0[(2 * c + 1) * HH] = o[1] * inv0;
    ob0[(8 + 2 * c) * HH] = o[4] * inv0;
    ob0[(9 + 2 * c) * HH] = o[5] * inv0;
    ob1[(2 * c) * HH]     = o[2] * inv1;
    ob1[(2 * c + 1) * HH] = o[3] * inv1;
    ob1[(8 + 2 * c) * HH] = o[6] * inv1;
    ob1[(9 + 2 * c) * HH] = o[7] * inv1;
}

// ---------------- custom "layernorm": c / var, var unbiased (N-1) -------------
__global__ void __launch_bounds__(256) ln_kernel(const float* __restrict__ x,
                                                 float* __restrict__ y)
{
    int row  = blockIdx.x * 8 + (threadIdx.x >> 5);
    int lane = threadIdx.x & 31;
    float4 t = ((const float4*)(x + (size_t)row * DD))[lane];
    float s = t.x + t.y + t.z + t.w;
#pragma unroll
    for (int o = 16; o; o >>= 1) s += __shfl_xor_sync(~0u, s, o);
    float m = s * (1.0f / DD);
    float cx = t.x - m, cy = t.y - m, cz = t.z - m, cw = t.w - m;
    float ss = cx * cx + cy * cy + cz * cz + cw * cw;
#pragma unroll
    for (int o = 16; o; o >>= 1) ss += __shfl_xor_sync(~0u, ss, o);
    float inv = (float)(DD - 1) / ss;
    float4 o4 = {cx * inv, cy * inv, cz * inv, cw * inv};
    ((float4*)(y + (size_t)row * DD))[lane] = o4;
}

// ---------------- launch --------------------------------------------------------
extern "C" void kernel_launch(void* const* d_in, const int* in_sizes, int n_in,
                              void* d_out, int out_size) {
    (void)in_sizes; (void)n_in; (void)out_size;
    const float* x_tgt = (const float*)d_in[0];
    const float* enc   = (const float*)d_in[1];
    const float* swq   = (const float*)d_in[2];
    const float* swk   = (const float*)d_in[3];
    const float* swv   = (const float*)d_in[4];
    const float* cwq   = (const float*)d_in[5];
    const float* cwk   = (const float*)d_in[6];
    const float* cwv   = (const float*)d_in[7];
    const float* w1    = (const float*)d_in[8];
    const float* b1    = (const float*)d_in[9];
    const float* w2    = (const float*)d_in[10];
    const float* b2    = (const float*)d_in[11];
    const float* w3    = (const float*)d_in[12];
    const float* b3    = (const float*)d_in[13];
    const float* w4    = (const float*)d_in[14];
    const float* b4    = (const float*)d_in[15];
    float* out = (float*)d_out;

    float *q1, *k1, *v1, *q2, *k2, *v2, *attn1, *attn2, *r1, *r2, *ln, *h;
    cudaGetSymbolAddress((void**)&q1,    g_q1);
    cudaGetSymbolAddress((void**)&k1,    g_k1);
    cudaGetSymbolAddress((void**)&v1,    g_v1);
    cudaGetSymbolAddress((void**)&q2,    g_q2);
    cudaGetSymbolAddress((void**)&k2,    g_k2);
    cudaGetSymbolAddress((void**)&v2,    g_v2);
    cudaGetSymbolAddress((void**)&attn1, g_attn1);
    cudaGetSymbolAddress((void**)&attn2, g_attn2);
    cudaGetSymbolAddress((void**)&r1,    g_r1);
    cudaGetSymbolAddress((void**)&r2,    g_r2);
    cudaGetSymbolAddress((void**)&ln,    g_ln);
    cudaGetSymbolAddress((void**)&h,     g_h);

    // dynamic smem: W panel + 2 A stages
    const int smQKV = DD * 72 * 4 + 2 * ATILE * 4;    // 36864 + 10240 = 47104
    const int smEpi = 128 * 40 * 4 + 2 * ATILE * 4;   // 30720
    const int smW3  = 128 * 72 * 4 + 2 * ATILE * 4;   // 47104
    const int smW4  = 512 * 40 * 4 + 2 * ATILE * 4;   // 92160 -> needs attribute
    cudaFuncSetAttribute(gemm_pipe_kernel<512, 128, 32, 1>,
                         cudaFuncAttributeMaxDynamicSharedMemorySize, smW4);

    const dim3 gQKV(12, MROWS / 64);              // all six projections
    const dim3 gA(SS / 64, BB * HH, 2);           // both attentions
    const dim3 gEpi(4, MROWS / 64);               // N=128, BN=32
    const dim3 gW3(8, MROWS / 64);                // N=512, BN=64
    const dim3 gW4(4, MROWS / 64);                // K=512 -> N=128, BN=32

    // all Q/K/V (self + cross) — independent of attention results
    gemm_qkv6_kernel<<<gQKV, 128, smQKV>>>(x_tgt, enc, swq, swk, swv,
                                           cwq, cwk, cwv,
                                           q1, k1, v1, q2, k2, v2);
    // both attentions (independent of each other)
    attn_mma_kernel<<<gA, 128>>>(q1, k1, v1, attn1, q2, k2, v2, attn2);
    // residual chain
    gemm_pipe_kernel<128, 128, 32, 1><<<gEpi, 128, smEpi>>>(attn1, w1, b1, x_tgt, r1);
    gemm_pipe_kernel<128, 128, 32, 1><<<gEpi, 128, smEpi>>>(attn2, w2, b2, r1, r2);
    ln_kernel<<<MROWS / 8, 256>>>(r2, ln);
    gemm_pipe_kernel<128, 512, 64, 2><<<gW3, 128, smW3>>>(ln, w3, b3, nullptr, h);
    gemm_pipe_kernel<512, 128, 32, 1><<<gW4, 128, smW4>>>(h, w4, b4, r2, out);
}

// round 7
// speedup vs baseline: 1.3500x; 1.0752x over previous
#include <cuda_runtime.h>
#include <cuda_bf16.h>

// Problem constants
#define BB 2
#define SS 2048
#define DD 128
#define HH 8
#define HDIM 16
#define DFF 512
#define MROWS (BB*SS)     // 4096
#define DCAT 256          // concat width of [attn1 | attn2]

// ---------------- scratch (device globals; no allocation allowed) -------------
__device__ float g_q1[BB*HH*SS*HDIM];
__device__ float g_k1[BB*HH*SS*HDIM];
__device__ float g_v1[BB*HH*SS*HDIM];
__device__ float g_q2[BB*HH*SS*HDIM];
__device__ float g_k2[BB*HH*SS*HDIM];
__device__ float g_v2[BB*HH*SS*HDIM];
__device__ float g_attn_cat[MROWS*DCAT];   // [row][0:128]=self, [128:256]=cross
__device__ float g_r2[BB*SS*DD];
__device__ float g_ln[BB*SS*DD];
__device__ float g_h[BB*SS*DFF];

// ---------------- helpers -----------------------------------------------------
__device__ __forceinline__ unsigned pack_bf16x2(float lo, float hi) {
    unsigned r;
    asm("cvt.rn.bf16x2.f32 %0, %1, %2;" : "=r"(r) : "f"(hi), "f"(lo));
    return r;
}
__device__ __forceinline__ float ex2(float x) {
    float y;
    asm("ex2.approx.ftz.f32 %0, %1;" : "=f"(y) : "f"(x));
    return y;
}
__device__ __forceinline__ unsigned tf32(float x) {
    unsigned r;
    asm("cvt.rna.tf32.f32 %0, %1;" : "=r"(r) : "f"(x));
    return r;
}
__device__ __forceinline__ void mma_bf16(
    float& c0, float& c1, float& c2, float& c3,
    unsigned a0, unsigned a1, unsigned a2, unsigned a3,
    unsigned b0, unsigned b1)
{
    asm("mma.sync.aligned.m16n8k16.row.col.f32.bf16.bf16.f32 "
        "{%0,%1,%2,%3},{%4,%5,%6,%7},{%8,%9},{%0,%1,%2,%3};"
        : "+f"(c0), "+f"(c1), "+f"(c2), "+f"(c3)
        : "r"(a0), "r"(a1), "r"(a2), "r"(a3), "r"(b0), "r"(b1));
}
__device__ __forceinline__ void mma_tf32(
    float& c0, float& c1, float& c2, float& c3,
    unsigned a0, unsigned a1, unsigned a2, unsigned a3,
    unsigned b0, unsigned b1)
{
    asm("mma.sync.aligned.m16n8k8.row.col.f32.tf32.tf32.f32 "
        "{%0,%1,%2,%3},{%4,%5,%6,%7},{%8,%9},{%0,%1,%2,%3};"
        : "+f"(c0), "+f"(c1), "+f"(c2), "+f"(c3)
        : "r"(a0), "r"(a1), "r"(a2), "r"(a3), "r"(b0), "r"(b1));
}
__device__ __forceinline__ void cp16(unsigned dst, const void* src) {
    asm volatile("cp.async.cg.shared.global [%0], [%1], 16;"
                 :: "r"(dst), "l"(src));
}
__device__ __forceinline__ void cp_commit() {
    asm volatile("cp.async.commit_group;");
}
__device__ __forceinline__ void cp_wait1() {
    asm volatile("cp.async.wait_group 1;");
}

#define ASTR 20           // A-tile smem stride (words): 20g+t conflict-free
#define ATILE (64*ASTR)   // one A stage, words

// ---------------- cp.async-pipelined W-resident tf32 GEMM ---------------------
// out = A(MxK) @ W(KxN) + epilogue.  256 thr, 8 warps: 4 in M x 2 in N
// (warp = 16 rows x BN/2 cols).  W panel (K x BN) smem-resident (tf32,
// stride BN+8 -> frag LDS conflict-free); A tiles (64x16 fp32) double-
// buffered via cp.async.
// EPI: 1 = +bias+res   2 = relu(+bias)
//      3 = fused r2:  W rows 0-127 from W, rows 128-255 from W2;
//          out = acc + bias + bias2 + res
template<int K, int N, int BN, int EPI>
__global__ void __launch_bounds__(256) gemm_pipe_kernel(
    const float* __restrict__ A, const float* __restrict__ W,
    const float* __restrict__ W2,
    const float* __restrict__ bias, const float* __restrict__ bias2,
    const float* __restrict__ res, float* __restrict__ out)
{
    constexpr int WSTR = BN + 8;
    constexpr int NT = BN / 16;          // n-tiles per warp
    constexpr int KT = K / 16;
    extern __shared__ unsigned smem[];
    unsigned* Ws = smem;                       // [K][WSTR] tf32
    float* As = (float*)(smem + K * WSTR);     // 2 x [64][ASTR] fp32
    const unsigned As_sh = (unsigned)__cvta_generic_to_shared(As);
    const int tid = threadIdx.x, warp = tid >> 5, lane = tid & 31;
    const int warp_m = warp >> 1, warp_n = warp & 1;
    const int g = lane >> 2, t = lane & 3;
    const int bm = blockIdx.y * 64, bn = blockIdx.x * BN;

    // stage whole weight panel (fp32 -> tf32), once
    for (int i = tid; i < K * (BN / 4); i += 256) {
        int row = i / (BN / 4), c = (i % (BN / 4)) * 4;
        float4 w4;
        if (EPI == 3 && row >= 128)
            w4 = *(const float4*)&W2[(size_t)(row - 128) * N + bn + c];
        else
            w4 = *(const float4*)&W[(size_t)row * N + bn + c];
        uint4 u = {tf32(w4.x), tf32(w4.y), tf32(w4.z), tf32(w4.w)};
        *(uint4*)&Ws[row * WSTR + c] = u;
    }

    // A prefetch: 64 rows x 16 k = 256 x 16B chunks, 1 per thread
    auto loadA = [&](int kt, int buf) {
        int row = tid >> 2, kc = (tid & 3) * 4;
        cp16(As_sh + (buf * ATILE + row * ASTR + kc) * 4,
             &A[(size_t)(bm + row) * K + kt * 16 + kc]);
        cp_commit();
    };
    loadA(0, 0);

    float acc[NT][4] = {};
    const int ra = warp_m * 16 + g;
    const int noff = warp_n * (BN / 2);

    for (int kt = 0; kt < KT; kt++) {
        if (kt + 1 < KT) loadA(kt + 1, (kt + 1) & 1);
        else cp_commit();                      // keep wait-group count aligned
        cp_wait1();
        __syncthreads();
        const float* Ab = As + (kt & 1) * ATILE;
#pragma unroll
        for (int kh = 0; kh < 16; kh += 8) {
            unsigned a0 = tf32(Ab[ra * ASTR + kh + t]);
            unsigned a1 = tf32(Ab[(ra + 8) * ASTR + kh + t]);
            unsigned a2 = tf32(Ab[ra * ASTR + kh + t + 4]);
            unsigned a3 = tf32(Ab[(ra + 8) * ASTR + kh + t + 4]);
            const int kr = kt * 16 + kh;
#pragma unroll
            for (int j = 0; j < NT; j++) {
                unsigned b0 = Ws[(kr + t) * WSTR + noff + j * 8 + g];
                unsigned b1 = Ws[(kr + t + 4) * WSTR + noff + j * 8 + g];
                mma_tf32(acc[j][0], acc[j][1], acc[j][2], acc[j][3],
                         a0, a1, a2, a3, b0, b1);
            }
        }
        __syncthreads();
    }

    const int r0 = bm + ra;
#pragma unroll
    for (int j = 0; j < NT; j++) {
        int c0 = bn + noff + j * 8 + 2 * t;
        if (EPI == 1 || EPI == 3) {
            float2 bi = *(const float2*)&bias[c0];
            if (EPI == 3) {
                float2 bi2 = *(const float2*)&bias2[c0];
                bi.x += bi2.x; bi.y += bi2.y;
            }
            float2 rA = *(const float2*)&res[(size_t)r0 * N + c0];
            float2 rB = *(const float2*)&res[(size_t)(r0 + 8) * N + c0];
            float2 oA = {acc[j][0] + bi.x + rA.x, acc[j][1] + bi.y + rA.y};
            float2 oB = {acc[j][2] + bi.x + rB.x, acc[j][3] + bi.y + rB.y};
            *(float2*)&out[(size_t)r0 * N + c0] = oA;
            *(float2*)&out[(size_t)(r0 + 8) * N + c0] = oB;
        } else {
            float2 bi = *(const float2*)&bias[c0];
            float2 oA = {fmaxf(acc[j][0] + bi.x, 0.f), fmaxf(acc[j][1] + bi.y, 0.f)};
            float2 oB = {fmaxf(acc[j][2] + bi.x, 0.f), fmaxf(acc[j][3] + bi.y, 0.f)};
            *(float2*)&out[(size_t)r0 * N + c0] = oA;
            *(float2*)&out[(size_t)(r0 + 8) * N + c0] = oB;
        }
    }
}

// ---------------- ALL-SIX QKV projections in one launch (pipelined) -----------
// grid (12, 64), 256 thr/8 warps: blockIdx.x>>1 = {sq, sk, sv, cq, ck, cv}
// (cross Q reads enc_out — the reference's quirk).  Scatter col c ->
// h=c&7, hd=c>>3 into [b][h][s][hd].
__global__ void __launch_bounds__(256) gemm_qkv6_kernel(
    const float* __restrict__ x_tgt, const float* __restrict__ enc,
    const float* __restrict__ swq, const float* __restrict__ swk,
    const float* __restrict__ swv, const float* __restrict__ cwq,
    const float* __restrict__ cwk, const float* __restrict__ cwv,
    float* __restrict__ q1, float* __restrict__ k1, float* __restrict__ v1,
    float* __restrict__ q2, float* __restrict__ k2, float* __restrict__ v2)
{
    const int which = blockIdx.x >> 1;
    const float* A = (which == 3) ? enc : x_tgt;
    const float* W; float* out;
    switch (which) {
        case 0: W = swq; out = q1; break;
        case 1: W = swk; out = k1; break;
        case 2: W = swv; out = v1; break;
        case 3: W = cwq; out = q2; break;
        case 4: W = cwk; out = k2; break;
        default: W = cwv; out = v2; break;
    }

    constexpr int WSTR = 72;
    extern __shared__ unsigned smem[];
    unsigned* Ws = smem;                       // [128][72]
    float* As = (float*)(smem + DD * WSTR);
    const unsigned As_sh = (unsigned)__cvta_generic_to_shared(As);
    const int tid = threadIdx.x, warp = tid >> 5, lane = tid & 31;
    const int warp_m = warp >> 1, warp_n = warp & 1;
    const int g = lane >> 2, t = lane & 3;
    const int bm = blockIdx.y * 64, bn = (blockIdx.x & 1) * 64;

    for (int i = tid; i < DD * 16; i += 256) {
        int row = i / 16, c = (i % 16) * 4;
        float4 w4 = *(const float4*)&W[(size_t)row * DD + bn + c];
        uint4 u = {tf32(w4.x), tf32(w4.y), tf32(w4.z), tf32(w4.w)};
        *(uint4*)&Ws[row * WSTR + c] = u;
    }

    auto loadA = [&](int kt, int buf) {
        int row = tid >> 2, kc = (tid & 3) * 4;
        cp16(As_sh + (buf * ATILE + row * ASTR + kc) * 4,
             &A[(size_t)(bm + row) * DD + kt * 16 + kc]);
        cp_commit();
    };
    loadA(0, 0);

    float acc[4][4] = {};
    const int ra = warp_m * 16 + g;
    const int noff = warp_n * 32;

    for (int kt = 0; kt < DD / 16; kt++) {
        if (kt + 1 < DD / 16) loadA(kt + 1, (kt + 1) & 1);
        else cp_commit();
        cp_wait1();
        __syncthreads();
        const float* Ab = As + (kt & 1) * ATILE;
#pragma unroll
        for (int kh = 0; kh < 16; kh += 8) {
            unsigned a0 = tf32(Ab[ra * ASTR + kh + t]);
            unsigned a1 = tf32(Ab[(ra + 8) * ASTR + kh + t]);
            unsigned a2 = tf32(Ab[ra * ASTR + kh + t + 4]);
            unsigned a3 = tf32(Ab[(ra + 8) * ASTR + kh + t + 4]);
            const int kr = kt * 16 + kh;
#pragma unroll
            for (int j = 0; j < 4; j++) {
                unsigned b0 = Ws[(kr + t) * WSTR + noff + j * 8 + g];
                unsigned b1 = Ws[(kr + t + 4) * WSTR + noff + j * 8 + g];
                mma_tf32(acc[j][0], acc[j][1], acc[j][2], acc[j][3],
                         a0, a1, a2, a3, b0, b1);
            }
        }
        __syncthreads();
    }

    const int r0 = bm + ra;
    const int bb0 = r0 >> 11, ss0 = r0 & (SS - 1);
    const int r1 = r0 + 8;
    const int bb1 = r1 >> 11, ss1 = r1 & (SS - 1);
#pragma unroll
    for (int j = 0; j < 4; j++) {
#pragma unroll
        for (int u = 0; u < 2; u++) {
            int c = bn + noff + j * 8 + 2 * t + u;
            int hh = c & 7, hd = c >> 3;
            out[(((size_t)(bb0 * HH + hh) * SS) + ss0) * HDIM + hd] = acc[j][u];
            out[(((size_t)(bb1 * HH + hh) * SS) + ss1) * HDIM + hd] = acc[j][2 + u];
        }
    }
}

// ---------------- flash attention (both attentions, concat output) ------------
// grid (S/64, B*H, 2): z=0 self -> cols 0-127, z=1 cross -> cols 128-255
// of attn_cat (stride DCAT).  128 thr (4 warps), warp owns 16 query rows.
#define VSTRIDE 136

__global__ void __launch_bounds__(128) attn_mma_kernel(
    const float* __restrict__ q1, const float* __restrict__ k1,
    const float* __restrict__ v1,
    const float* __restrict__ q2, const float* __restrict__ k2,
    const float* __restrict__ v2, float* __restrict__ ocat)
{
    const float* q = blockIdx.z ? q2 : q1;
    const float* k = blockIdx.z ? k2 : k1;
    const float* v = blockIdx.z ? v2 : v1;
    float* out = ocat + (blockIdx.z ? DD : 0);

    __shared__ unsigned Ks[128][8];
    __shared__ __nv_bfloat16 Vs[16][VSTRIDE];
    const int tid = threadIdx.x, w = tid >> 5, lane = tid & 31;
    const int bh = blockIdx.y, b = bh >> 3, h = bh & 7;
    const int g = lane >> 2, c = lane & 3;
    const size_t head = (size_t)bh * SS;
    const int qrow = blockIdx.x * 64 + w * 16;

    const float sc = 0.25f * 1.4426950408889634f;
    unsigned qa[4];
    {
        const float* r0 = q + (head + qrow + g) * HDIM;
        const float* r1 = r0 + 8 * HDIM;
        float2 t;
        t = *(const float2*)(r0 + 2 * c);     qa[0] = pack_bf16x2(t.x * sc, t.y * sc);
        t = *(const float2*)(r1 + 2 * c);     qa[1] = pack_bf16x2(t.x * sc, t.y * sc);
        t = *(const float2*)(r0 + 2 * c + 8); qa[2] = pack_bf16x2(t.x * sc, t.y * sc);
        t = *(const float2*)(r1 + 2 * c + 8); qa[3] = pack_bf16x2(t.x * sc, t.y * sc);
    }

    float o[8] = {0, 0, 0, 0, 0, 0, 0, 0};
    float l0 = 0.f, l1 = 0.f;

    for (int kt = 0; kt < SS / 128; kt++) {
        __syncthreads();
        const float4* ksrc = (const float4*)(k + (head + kt * 128) * HDIM);
        const float4* vsrc = (const float4*)(v + (head + kt * 128) * HDIM);
#pragma unroll
        for (int i = 0; i < 4; i++) {
            int idx = tid + i * 128;
            int key = idx >> 2, f4 = idx & 3;
            float4 t = ksrc[idx];
            Ks[key][f4 * 2]     = pack_bf16x2(t.x, t.y);
            Ks[key][f4 * 2 + 1] = pack_bf16x2(t.z, t.w);
            float4 u = vsrc[idx];
            Vs[f4 * 4 + 0][key] = __float2bfloat16(u.x);
            Vs[f4 * 4 + 1][key] = __float2bfloat16(u.y);
            Vs[f4 * 4 + 2][key] = __float2bfloat16(u.z);
            Vs[f4 * 4 + 3][key] = __float2bfloat16(u.w);
        }
        __syncthreads();

#pragma unroll
        for (int kc = 0; kc < 8; kc++) {
            float s0 = 0, s1 = 0, s2 = 0, s3 = 0, s4 = 0, s5 = 0, s6 = 0, s7 = 0;
            {
                unsigned b0 = Ks[kc * 16 + g][c];
                unsigned b1 = Ks[kc * 16 + g][c + 4];
                mma_bf16(s0, s1, s2, s3, qa[0], qa[1], qa[2], qa[3], b0, b1);
                b0 = Ks[kc * 16 + 8 + g][c];
                b1 = Ks[kc * 16 + 8 + g][c + 4];
                mma_bf16(s4, s5, s6, s7, qa[0], qa[1], qa[2], qa[3], b0, b1);
            }
            float p0 = ex2(s0), p1 = ex2(s1), p2 = ex2(s2), p3 = ex2(s3);
            float p4 = ex2(s4), p5 = ex2(s5), p6 = ex2(s6), p7 = ex2(s7);
            l0 += (p0 + p1) + (p4 + p5);
            l1 += (p2 + p3) + (p6 + p7);
            unsigned A0 = pack_bf16x2(p0, p1);
            unsigned A1 = pack_bf16x2(p2, p3);
            unsigned A2 = pack_bf16x2(p4, p5);
            unsigned A3 = pack_bf16x2(p6, p7);
            unsigned vb0 = *(const unsigned*)&Vs[g][kc * 16 + 2 * c];
            unsigned vb1 = *(const unsigned*)&Vs[g][kc * 16 + 2 * c + 8];
            mma_bf16(o[0], o[1], o[2], o[3], A0, A1, A2, A3, vb0, vb1);
            vb0 = *(const unsigned*)&Vs[8 + g][kc * 16 + 2 * c];
            vb1 = *(const unsigned*)&Vs[8 + g][kc * 16 + 2 * c + 8];
            mma_bf16(o[4], o[5], o[6], o[7], A0, A1, A2, A3, vb0, vb1);
        }
    }

    l0 += __shfl_xor_sync(~0u, l0, 1); l0 += __shfl_xor_sync(~0u, l0, 2);
    l1 += __shfl_xor_sync(~0u, l1, 1); l1 += __shfl_xor_sync(~0u, l1, 2);
    const float inv0 = 1.0f / l0, inv1 = 1.0f / l1;

    // col = hd*8 + h (reference merge), row stride DCAT
    float* ob0 = out + ((size_t)(b * SS) + qrow + g) * DCAT + h;
    float* ob1 = out + ((size_t)(b * SS) + qrow + 8 + g) * DCAT + h;
    ob0[(2 * c) * HH]     = o[0] * inv0;
    ob0[(2 * c + 1) * HH] = o[1] * inv0;
    ob0[(8 + 2 * c) * HH] = o[4] * inv0;
    ob0[(9 + 2 * c) * HH] = o[5] * inv0;
    ob1[(2 * c) * HH]     = o[2] * inv1;
    ob1[(2 * c + 1) * HH] = o[3] * inv1;
    ob1[(8 + 2 * c) * HH] = o[6] * inv1;
    ob1[(9 + 2 * c) * HH] = o[7] * inv1;
}

// ---------------- custom "layernorm": c / var, var unbiased (N-1) -------------
__global__ void __launch_bounds__(256) ln_kernel(const float* __restrict__ x,
                                                 float* __restrict__ y)
{
    int row  = blockIdx.x * 8 + (threadIdx.x >> 5);
    int lane = threadIdx.x & 31;
    float4 t = ((const float4*)(x + (size_t)row * DD))[lane];
    float s = t.x + t.y + t.z + t.w;
#pragma unroll
    for (int o = 16; o; o >>= 1) s += __shfl_xor_sync(~0u, s, o);
    float m = s * (1.0f / DD);
    float cx = t.x - m, cy = t.y - m, cz = t.z - m, cw = t.w - m;
    float ss = cx * cx + cy * cy + cz * cz + cw * cw;
#pragma unroll
    for (int o = 16; o; o >>= 1) ss += __shfl_xor_sync(~0u, ss, o);
    float inv = (float)(DD - 1) / ss;
    float4 o4 = {cx * inv, cy * inv, cz * inv, cw * inv};
    ((float4*)(y + (size_t)row * DD))[lane] = o4;
}

// ---------------- launch --------------------------------------------------------
extern "C" void kernel_launch(void* const* d_in, const int* in_sizes, int n_in,
                              void* d_out, int out_size) {
    (void)in_sizes; (void)n_in; (void)out_size;
    const float* x_tgt = (const float*)d_in[0];
    const float* enc   = (const float*)d_in[1];
    const float* swq   = (const float*)d_in[2];
    const float* swk   = (const float*)d_in[3];
    const float* swv   = (const float*)d_in[4];
    const float* cwq   = (const float*)d_in[5];
    const float* cwk   = (const float*)d_in[6];
    const float* cwv   = (const float*)d_in[7];
    const float* w1    = (const float*)d_in[8];
    const float* b1    = (const float*)d_in[9];
    const float* w2    = (const float*)d_in[10];
    const float* b2    = (const float*)d_in[11];
    const float* w3    = (const float*)d_in[12];
    const float* b3    = (const float*)d_in[13];
    const float* w4    = (const float*)d_in[14];
    const float* b4    = (const float*)d_in[15];
    float* out = (float*)d_out;

    float *q1, *k1, *v1, *q2, *k2, *v2, *acat, *r2, *ln, *h;
    cudaGetSymbolAddress((void**)&q1,   g_q1);
    cudaGetSymbolAddress((void**)&k1,   g_k1);
    cudaGetSymbolAddress((void**)&v1,   g_v1);
    cudaGetSymbolAddress((void**)&q2,   g_q2);
    cudaGetSymbolAddress((void**)&k2,   g_k2);
    cudaGetSymbolAddress((void**)&v2,   g_v2);
    cudaGetSymbolAddress((void**)&acat, g_attn_cat);
    cudaGetSymbolAddress((void**)&r2,   g_r2);
    cudaGetSymbolAddress((void**)&ln,   g_ln);
    cudaGetSymbolAddress((void**)&h,    g_h);

    // dynamic smem: W panel + 2 A stages
    const int smQKV = DD * 72 * 4 + 2 * ATILE * 4;    // 47104
    const int smR2  = 256 * 40 * 4 + 2 * ATILE * 4;   // 51200 -> attribute
    const int smW3  = 128 * 72 * 4 + 2 * ATILE * 4;   // 47104
    const int smW4  = 512 * 40 * 4 + 2 * ATILE * 4;   // 92160 -> attribute
    cudaFuncSetAttribute(gemm_pipe_kernel<256, 128, 32, 3>,
                         cudaFuncAttributeMaxDynamicSharedMemorySize, smR2);
    cudaFuncSetAttribute(gemm_pipe_kernel<512, 128, 32, 1>,
                         cudaFuncAttributeMaxDynamicSharedMemorySize, smW4);

    const dim3 gQKV(12, MROWS / 64);              // all six projections
    const dim3 gA(SS / 64, BB * HH, 2);           // both attentions
    const dim3 gR2(4, MROWS / 64);                // fused r2 (K=256)
    const dim3 gW3(8, MROWS / 64);                // N=512, BN=64
    const dim3 gW4(4, MROWS / 64);                // K=512 -> N=128

    gemm_qkv6_kernel<<<gQKV, 256, smQKV>>>(x_tgt, enc, swq, swk, swv,
                                           cwq, cwk, cwv,
                                           q1, k1, v1, q2, k2, v2);
    attn_mma_kernel<<<gA, 128>>>(q1, k1, v1, q2, k2, v2, acat);
    // r2 = [attn1|attn2] @ [w1;w2] + b1 + b2 + x_tgt
    gemm_pipe_kernel<256, 128, 32, 3><<<gR2, 256, smR2>>>(
        acat, w1, w2, b1, b2, x_tgt, r2);
    ln_kernel<<<MROWS / 8, 256>>>(r2, ln);
    gemm_pipe_kernel<128, 512, 64, 2><<<gW3, 256, smW3>>>(
        ln, w3, nullptr, b3, nullptr, nullptr, h);
    gemm_pipe_kernel<512, 128, 32, 1><<<gW4, 256, smW4>>>(
        h, w4, nullptr, b4, nullptr, r2, out);
}